// round 6
// baseline (speedup 1.0000x reference)
#include <cuda_runtime.h>
#include <math.h>

// Problem dims
#define TT   8192
#define DIN  2048
#define DD   512
#define HH   512
#define AA   18
#define H3   (3*HH)       // 1536
#define GCTAS 64          // persistent GRU CTAs (all co-resident, 64 < 148 SMs)

// Output layout (flattened concat of (policy, value, hT))
#define P_OFF  0
#define V_OFF  (TT*AA)            // 147456
#define HT_OFF (TT*AA + TT)       // 155648

// ---------------- device scratch (no allocations allowed) ----------------
__device__ float g_z1[TT*DD];
__device__ float g_z2[TT*DD];
__device__ float g_X [TT*H3];
__device__ float g_seq[TT*HH];

// Per-CTA mailbox: 8 h-values + publish flag in one 128B line (no false sharing,
// flag and payload travel together through L2).
struct __align__(128) Slot {
    float h[8];
    unsigned flag;
    unsigned pad[23];
};
__device__ Slot g_slot[2][GCTAS];

__device__ __forceinline__ float sigmoidf_(float x) {
    return 1.0f / (1.0f + __expf(-x));
}

// ---------------- fp32 SGEMM: C = act(A[MxK] @ B[KxN] + bias[N]) ----------------
// 128x128 tile, BK=8, 256 threads, 8x8 micro-tile per thread.
template<bool RELU>
__global__ __launch_bounds__(256)
void sgemm_bias(const float* __restrict__ A, const float* __restrict__ B,
                const float* __restrict__ bias, float* __restrict__ C,
                int M, int N, int K)
{
    __shared__ float As[8][128];
    __shared__ float Bs[8][128];

    const int tid = threadIdx.x;
    const int bm = blockIdx.y * 128;
    const int bn = blockIdx.x * 128;

    const int arow = tid >> 1;
    const int acol = (tid & 1) << 2;
    const int brow = tid >> 5;
    const int bcol = (tid & 31) << 2;

    const int ty = tid >> 4, tx = tid & 15;
    const int row0 = ty << 3;
    const int col0 = tx << 3;

    float c[8][8];
    #pragma unroll
    for (int i = 0; i < 8; i++)
        #pragma unroll
        for (int j = 0; j < 8; j++) c[i][j] = 0.0f;

    for (int k0 = 0; k0 < K; k0 += 8) {
        float4 a4 = *(const float4*)&A[(size_t)(bm + arow) * K + k0 + acol];
        As[acol + 0][arow] = a4.x;
        As[acol + 1][arow] = a4.y;
        As[acol + 2][arow] = a4.z;
        As[acol + 3][arow] = a4.w;
        *(float4*)&Bs[brow][bcol] =
            *(const float4*)&B[(size_t)(k0 + brow) * N + bn + bcol];
        __syncthreads();

        #pragma unroll
        for (int kk = 0; kk < 8; kk++) {
            float4 a0 = *(const float4*)&As[kk][row0];
            float4 a1 = *(const float4*)&As[kk][row0 + 4];
            float4 b0 = *(const float4*)&Bs[kk][col0];
            float4 b1 = *(const float4*)&Bs[kk][col0 + 4];
            float ar[8] = {a0.x,a0.y,a0.z,a0.w,a1.x,a1.y,a1.z,a1.w};
            float br[8] = {b0.x,b0.y,b0.z,b0.w,b1.x,b1.y,b1.z,b1.w};
            #pragma unroll
            for (int i = 0; i < 8; i++)
                #pragma unroll
                for (int j = 0; j < 8; j++)
                    c[i][j] = fmaf(ar[i], br[j], c[i][j]);
        }
        __syncthreads();
    }

    #pragma unroll
    for (int i = 0; i < 8; i++) {
        #pragma unroll
        for (int j = 0; j < 8; j++) {
            float v = c[i][j] + bias[bn + col0 + j];
            if (RELU) v = fmaxf(v, 0.0f);
            C[(size_t)(bm + row0 + i) * N + bn + col0 + j] = v;
        }
    }
}

// ---------------- init: mailbox slot 0 <- prev_hidden, flags <- 0 ----------------
__global__ void init_kernel(const float* __restrict__ prev_hidden)
{
    int i = threadIdx.x;                       // 512 threads
    g_slot[0][i >> 3].h[i & 7] = prev_hidden[i];
    if (i < GCTAS) {
        g_slot[0][i].flag = 0;                 // h_0 published with flag 0
        g_slot[1][i].flag = 0;                 // stale from previous graph replay
    }
}

// ---------------- persistent GRU scan ----------------
// 64 CTAs x 192 threads. CTA `blk` owns h-indices [blk*8, blk*8+8) -> 24 rec cols.
// tid = col*8 + seg: col in 0..23 (gate*8+j), seg in 0..7 (64-wide K segment).
// Each thread caches its 64 Ug weights in registers.
// Step t: read h_t from g_slot[t&1] (flag >= t), publish h_{t+1} to g_slot[~t&1]
// with flag t+1 via st.release.
__global__ __launch_bounds__(192, 1)
void gru_kernel(const float* __restrict__ Ug, const float* __restrict__ bg,
                float* __restrict__ out)
{
    __shared__ float sh_h[HH];
    __shared__ float sh_rec[24];
    __shared__ float sh_x[24];

    const int tid = threadIdx.x;
    const int blk = blockIdx.x;
    const int col = tid >> 3;        // 0..23
    const int seg = tid & 7;         // 0..7  (low 3 lane bits -> shfl reduction)
    const int gate = col >> 3;       // 0..2
    const int j = col & 7;           // 0..7
    const int gcol = gate * HH + blk * 8 + j;

    float w[64];
    #pragma unroll
    for (int i = 0; i < 64; i++)
        w[i] = Ug[(size_t)(seg * 64 + i) * H3 + gcol];

    const float brec = bg[H3 + gcol];          // bg[1] row

    float hlast = 0.0f;

    for (int t = 0; t < TT; t++) {
        const int par = t & 1;

        // Prefetch this step's X values (h-independent)
        float xv = 0.0f;
        if (tid < 24)
            xv = g_X[(size_t)t * H3 + (tid >> 3) * HH + blk * 8 + (tid & 7)];

        // Poll all 64 slots in parallel; flag and payload share an L2 line.
        if (tid < GCTAS) {
            const unsigned* fp = &g_slot[par][tid].flag;
            unsigned f;
            do {
                asm volatile("ld.acquire.gpu.global.u32 %0, [%1];"
                             : "=r"(f) : "l"(fp));
            } while ((int)f < t);
            const float4* hp = (const float4*)g_slot[par][tid].h;
            float4 a = __ldcg(hp);
            float4 b = __ldcg(hp + 1);
            *(float4*)&sh_h[tid * 8]     = a;
            *(float4*)&sh_h[tid * 8 + 4] = b;
        }
        if (tid < 24) sh_x[tid] = xv;
        __syncthreads();                       // bar1: h staged

        // 512-long dot, 64 elems/thread, 4 accumulator chains
        const float4* hseg = (const float4*)&sh_h[seg * 64];
        float a0 = 0.f, a1 = 0.f, a2 = 0.f, a3 = 0.f;
        #pragma unroll
        for (int i = 0; i < 16; i++) {
            float4 h4 = hseg[i];
            a0 = fmaf(w[4*i+0], h4.x, a0);
            a1 = fmaf(w[4*i+1], h4.y, a1);
            a2 = fmaf(w[4*i+2], h4.z, a2);
            a3 = fmaf(w[4*i+3], h4.w, a3);
        }
        float r = (a0 + a1) + (a2 + a3);
        // reduce over seg (lane bits 0..2)
        r += __shfl_xor_sync(0xffffffffu, r, 1);
        r += __shfl_xor_sync(0xffffffffu, r, 2);
        r += __shfl_xor_sync(0xffffffffu, r, 4);
        if (seg == 0) sh_rec[col] = r + brec;

        // capture hprev BEFORE bar2: after bar2, warps 0/1 of step t+1 may
        // overwrite sh_h while warp 0 is still in the gate section.
        float hprev = 0.0f;
        if (tid < 8) hprev = sh_h[blk * 8 + tid];
        __syncthreads();                       // bar2: rec ready

        if (tid < 8) {
            const float rz = sh_rec[tid], rr = sh_rec[8 + tid], rh = sh_rec[16 + tid];
            const float xz = sh_x[tid],   xr = sh_x[8 + tid],   xh = sh_x[16 + tid];
            const float zt = sigmoidf_(xz + rz);
            const float rt = sigmoidf_(xr + rr);
            const float hh = sigmoidf_(xh + rt * rh);
            const float hn = zt * hprev + (1.0f - zt) * hh;
            g_seq[(size_t)t * HH + blk * 8 + tid] = hn;
            g_slot[par ^ 1][blk].h[tid] = hn;
            hlast = hn;
        }
        // publish: data stores (lanes 0..7) ordered before lane 0's release
        // store by the warp-level barrier; only warp 0 participates.
        if (tid < 32) {
            __syncwarp();
            if (tid == 0) {
                unsigned* fp = &g_slot[par ^ 1][blk].flag;
                asm volatile("st.release.gpu.global.u32 [%0], %1;"
                             :: "l"(fp), "r"((unsigned)(t + 1)) : "memory");
            }
        }
        // no bar3: next iteration's poll (warps 0,1) may run ahead; all shared
        // state it touches is protected by bar1/bar2 of step t+1.
    }

    if (tid < 8) out[HT_OFF + blk * 8 + tid] = hlast;
}

// ---------------- policy softmax + value head ----------------
// One warp per timestep; lanes 0..17 -> policy logits, lane 18 -> value.
__global__ __launch_bounds__(256)
void policy_value_kernel(const float* __restrict__ Wp, const float* __restrict__ bp,
                         const float* __restrict__ Wv, const float* __restrict__ bv,
                         float* __restrict__ out)
{
    __shared__ float srow[8][HH];
    const int warp = threadIdx.x >> 5;
    const int lane = threadIdx.x & 31;
    const int t = blockIdx.x * 8 + warp;

    const float4* rp = (const float4*)&g_seq[(size_t)t * HH];
    float4* sp = (float4*)&srow[warp][0];
    for (int i = lane; i < HH / 4; i += 32) sp[i] = rp[i];
    __syncwarp();

    const float* wcol; int stride; float acc;
    if (lane < AA)       { wcol = Wp + lane; stride = AA; acc = bp[lane]; }
    else if (lane == AA) { wcol = Wv;        stride = 1;  acc = bv[0];    }
    else                 { wcol = Wv;        stride = 0;  acc = 0.0f;     }

    #pragma unroll 4
    for (int k = 0; k < HH; k++)
        acc = fmaf(srow[warp][k], wcol[(size_t)k * stride], acc);

    float lv = (lane < AA) ? acc : -INFINITY;
    float m = lv;
    #pragma unroll
    for (int o = 16; o; o >>= 1) m = fmaxf(m, __shfl_xor_sync(0xffffffffu, m, o));
    float e = (lane < AA) ? __expf(acc - m) : 0.0f;
    float sum = e;
    #pragma unroll
    for (int o = 16; o; o >>= 1) sum += __shfl_xor_sync(0xffffffffu, sum, o);

    if (lane < AA)  out[P_OFF + (size_t)t * AA + lane] = e / sum;
    if (lane == AA) out[V_OFF + t] = acc;
}

// ---------------- launch ----------------
extern "C" void kernel_launch(void* const* d_in, const int* in_sizes, int n_in,
                              void* d_out, int out_size)
{
    (void)in_sizes; (void)n_in; (void)out_size;
    const float* x    = (const float*)d_in[0];
    const float* ph   = (const float*)d_in[1];
    const float* W1   = (const float*)d_in[2];
    const float* b1   = (const float*)d_in[3];
    const float* W2   = (const float*)d_in[4];
    const float* b2   = (const float*)d_in[5];
    const float* Wg   = (const float*)d_in[6];
    const float* Ug   = (const float*)d_in[7];
    const float* bg   = (const float*)d_in[8];
    const float* Wp   = (const float*)d_in[9];
    const float* bp   = (const float*)d_in[10];
    const float* Wv   = (const float*)d_in[11];
    const float* bv   = (const float*)d_in[12];
    float* out = (float*)d_out;

    float *z1, *z2, *X;
    cudaGetSymbolAddress((void**)&z1, g_z1);
    cudaGetSymbolAddress((void**)&z2, g_z2);
    cudaGetSymbolAddress((void**)&X,  g_X);

    sgemm_bias<true ><<<dim3(DD/128, TT/128), 256>>>(x,  W1, b1, z1, TT, DD, DIN);
    sgemm_bias<true ><<<dim3(DD/128, TT/128), 256>>>(z1, W2, b2, z2, TT, DD, DD);
    sgemm_bias<false><<<dim3(H3/128, TT/128), 256>>>(z2, Wg, bg, X,  TT, H3, DD);

    init_kernel<<<1, 512>>>(ph);
    gru_kernel<<<GCTAS, 192>>>(Ug, bg, out);
    policy_value_kernel<<<TT/8, 256>>>(Wp, bp, Wv, bv, out);
}

// round 12
// speedup vs baseline: 1.8340x; 1.8340x over previous
#include <cuda_runtime.h>
#include <math.h>

// Problem dims
#define TT   8192
#define DIN  2048
#define DD   512
#define HH   512
#define AA   18
#define H3   (3*HH)       // 1536

// GRU scan config: 32 persistent CTAs, 16 h-values each, 48 gate-cols each.
#define GC   32
#define HPC  16           // h per CTA
#define CPC  48           // rec columns per CTA (3 gates x 16)
#define NCH  6            // publish chunks per CTA (3 h-values + flag per 16B)
#define GTHREADS 384

// Output layout (flattened concat of (policy, value, hT))
#define P_OFF  0
#define V_OFF  (TT*AA)            // 147456
#define HT_OFF (TT*AA + TT)       // 155648

// ---------------- device scratch (no allocations allowed) ----------------
__device__ float g_z1[TT*DD];
__device__ float g_z2[TT*DD];
__device__ float g_X [TT*H3];
__device__ float g_seq[TT*HH];
// Publish buffer: one 128B line per (parity, producer). Each 16B chunk carries
// 3 h-values + the step flag in .w, written with ONE single-copy-atomic
// st.release.gpu.b128 — a matching flag implies valid payload in the same read.
__device__ __align__(128) float4 g_chunk[2][GC][8];

__device__ __forceinline__ float sigmoidf_(float x) {
    return 1.0f / (1.0f + __expf(-x));
}

// 16B single-copy-atomic acquire load (sm_90+: b128 with memory-consistency
// qualifiers). Guarantees flag+payload are read as one unit, and orders the
// causality chain producer-release -> consumer-acquire.
__device__ __forceinline__ float4 ld_acq128(const float4* p) {
    float4 v;
    asm volatile(
        "{\n\t"
        ".reg .b128 q;\n\t"
        ".reg .b64 lo, hi;\n\t"
        "ld.global.acquire.gpu.b128 q, [%4];\n\t"
        "mov.b128 {lo, hi}, q;\n\t"
        "mov.b64 {%0, %1}, lo;\n\t"
        "mov.b64 {%2, %3}, hi;\n\t"
        "}"
        : "=f"(v.x), "=f"(v.y), "=f"(v.z), "=f"(v.w) : "l"(p));
    return v;
}
// 16B single-copy-atomic release store.
__device__ __forceinline__ void st_rel128(float4* p, float4 v) {
    asm volatile(
        "{\n\t"
        ".reg .b128 q;\n\t"
        ".reg .b64 lo, hi;\n\t"
        "mov.b64 lo, {%1, %2};\n\t"
        "mov.b64 hi, {%3, %4};\n\t"
        "mov.b128 q, {lo, hi};\n\t"
        "st.global.release.gpu.b128 [%0], q;\n\t"
        "}"
        :: "l"(p), "f"(v.x), "f"(v.y), "f"(v.z), "f"(v.w) : "memory");
}

// ---------------- fp32 SGEMM: C = act(A[MxK] @ B[KxN] + bias[N]) ----------------
template<bool RELU>
__global__ __launch_bounds__(256)
void sgemm_bias(const float* __restrict__ A, const float* __restrict__ B,
                const float* __restrict__ bias, float* __restrict__ C,
                int M, int N, int K)
{
    __shared__ float As[8][128];
    __shared__ float Bs[8][128];

    const int tid = threadIdx.x;
    const int bm = blockIdx.y * 128;
    const int bn = blockIdx.x * 128;

    const int arow = tid >> 1;
    const int acol = (tid & 1) << 2;
    const int brow = tid >> 5;
    const int bcol = (tid & 31) << 2;

    const int ty = tid >> 4, tx = tid & 15;
    const int row0 = ty << 3;
    const int col0 = tx << 3;

    float c[8][8];
    #pragma unroll
    for (int i = 0; i < 8; i++)
        #pragma unroll
        for (int j = 0; j < 8; j++) c[i][j] = 0.0f;

    for (int k0 = 0; k0 < K; k0 += 8) {
        float4 a4 = *(const float4*)&A[(size_t)(bm + arow) * K + k0 + acol];
        As[acol + 0][arow] = a4.x;
        As[acol + 1][arow] = a4.y;
        As[acol + 2][arow] = a4.z;
        As[acol + 3][arow] = a4.w;
        *(float4*)&Bs[brow][bcol] =
            *(const float4*)&B[(size_t)(k0 + brow) * N + bn + bcol];
        __syncthreads();

        #pragma unroll
        for (int kk = 0; kk < 8; kk++) {
            float4 a0 = *(const float4*)&As[kk][row0];
            float4 a1 = *(const float4*)&As[kk][row0 + 4];
            float4 b0 = *(const float4*)&Bs[kk][col0];
            float4 b1 = *(const float4*)&Bs[kk][col0 + 4];
            float ar[8] = {a0.x,a0.y,a0.z,a0.w,a1.x,a1.y,a1.z,a1.w};
            float br[8] = {b0.x,b0.y,b0.z,b0.w,b1.x,b1.y,b1.z,b1.w};
            #pragma unroll
            for (int i = 0; i < 8; i++)
                #pragma unroll
                for (int j = 0; j < 8; j++)
                    c[i][j] = fmaf(ar[i], br[j], c[i][j]);
        }
        __syncthreads();
    }

    #pragma unroll
    for (int i = 0; i < 8; i++) {
        #pragma unroll
        for (int j = 0; j < 8; j++) {
            float v = c[i][j] + bias[bn + col0 + j];
            if (RELU) v = fmaxf(v, 0.0f);
            C[(size_t)(bm + row0 + i) * N + bn + col0 + j] = v;
        }
    }
}

// ---------------- init: publish h0 (flag 0) into parity 0; clear parity 1 ----------------
__global__ void init_kernel(const float* __restrict__ prev_hidden)
{
    int t = threadIdx.x;                       // 192 threads = GC*NCH
    if (t < GC * NCH) {
        int p = t / NCH, c = t % NCH;
        int b = p * HPC + c * 3;
        float4 v;
        v.x = prev_hidden[b];
        v.y = (c * 3 + 1 < HPC) ? prev_hidden[b + 1] : 0.0f;
        v.z = (c * 3 + 2 < HPC) ? prev_hidden[b + 2] : 0.0f;
        v.w = __uint_as_float(0u);             // flag = step 0
        st_rel128(&g_chunk[0][p][c], v);
        // clear stale parity-1 flags from the previous graph replay;
        // flag 0 never matches an odd step number.
        float4 z = make_float4(0.0f, 0.0f, 0.0f, __uint_as_float(0u));
        st_rel128(&g_chunk[1][p][c], z);
    }
}

// ---------------- persistent GRU scan ----------------
// 32 CTAs x 384 threads. CTA `blk` owns h[blk*16 .. blk*16+16) -> 48 rec cols.
// tid = col*8 + seg: col 0..47, seg 0..7 (64-wide K segment, in lane bits 0..2
// so the K-reduction is 3 shfl_xor).
// Handoff: 16B atomic chunks {h0,h1,h2,flag}; acquire-poll, release-publish.
// sh_h uses a 68-float seg stride so the 8 seg streams are bank-conflict-free.
__global__ __launch_bounds__(GTHREADS, 1)
void gru_kernel(const float* __restrict__ Ug, const float* __restrict__ bg,
                const float* __restrict__ prev_hidden, float* __restrict__ out)
{
    __shared__ float sh_h[8 * 68];     // phys(l) = (l>>6)*68 + (l&63)
    __shared__ float sh_rec[CPC];
    __shared__ float sh_x[2][CPC];

    const int tid = threadIdx.x;
    const int blk = blockIdx.x;
    const int col = tid >> 3;          // 0..47
    const int seg = tid & 7;           // 0..7
    const int gate = col >> 4;         // 0..2
    const int j = col & 15;            // 0..15
    const int gcol = gate * HH + blk * HPC + j;

    // Weight slice in registers: w[i] = Ug[seg*64+i][gcol]
    float w[64];
    #pragma unroll
    for (int i = 0; i < 64; i++)
        w[i] = Ug[(size_t)(seg * 64 + i) * H3 + gcol];

    const float brec = bg[H3 + gcol];

    // Poller mapping: threads 0..185 each own one (producer != blk, chunk).
    const bool isPoll = (tid < (GC - 1) * NCH);
    int pp = 0, pc = 0, pbase = 0;
    if (isPoll) {
        int q = tid / NCH;
        pc = tid - q * NCH;
        pp = q + (q >= blk ? 1 : 0);
        pbase = pp * HPC + pc * 3;
    }
    // X loaders: threads 192..239 load this CTA's 48 X-values per step.
    const bool isX = (tid >= 192 && tid < 192 + CPC);
    const int xcol = tid - 192;
    const int xgc = (xcol >> 4) * HH + blk * HPC + (xcol & 15);

    // Gate lanes (warp 0, lanes 0..15) keep their own h in a register.
    float hprev = 0.0f;
    if (tid < HPC) {
        hprev = prev_hidden[blk * HPC + tid];
        int l = blk * HPC + tid;               // stage own slice for t=0
        sh_h[(l >> 6) * 68 + (l & 63)] = hprev;
    }

    for (int t = 0; t < TT; t++) {
        const int par = t & 1;

        if (isX) sh_x[par][xcol] = g_X[(size_t)t * H3 + xgc];

        if (isPoll) {
            const float4* cp = &g_chunk[par][pp][pc];
            float4 v;
            do { v = ld_acq128(cp); } while (__float_as_uint(v.w) != (unsigned)t);
            int l0 = pbase;
            sh_h[(l0 >> 6) * 68 + (l0 & 63)] = v.x;
            if (pc * 3 + 1 < HPC) { int l = pbase + 1; sh_h[(l >> 6) * 68 + (l & 63)] = v.y; }
            if (pc * 3 + 2 < HPC) { int l = pbase + 2; sh_h[(l >> 6) * 68 + (l & 63)] = v.z; }
        }
        __syncthreads();                       // bar1: h + x staged

        // 512-long dot: 64 elems/thread, 4 accumulator chains, conflict-free LDS
        const float4* hp = (const float4*)&sh_h[seg * 68];
        float a0 = 0.f, a1 = 0.f, a2 = 0.f, a3 = 0.f;
        #pragma unroll
        for (int i = 0; i < 16; i++) {
            float4 h4 = hp[i];
            a0 = fmaf(w[4*i+0], h4.x, a0);
            a1 = fmaf(w[4*i+1], h4.y, a1);
            a2 = fmaf(w[4*i+2], h4.z, a2);
            a3 = fmaf(w[4*i+3], h4.w, a3);
        }
        float r = (a0 + a1) + (a2 + a3);
        r += __shfl_xor_sync(0xffffffffu, r, 1);
        r += __shfl_xor_sync(0xffffffffu, r, 2);
        r += __shfl_xor_sync(0xffffffffu, r, 4);
        if (seg == 0) sh_rec[col] = r + brec;
        __syncthreads();                       // bar2: rec ready

        // Warp 0: gates + publish. Other warps run ahead to the next poll
        // (their sh writes target next-parity x / foreign-producer h slots,
        // and all reads they will do are fenced by bar1/bar2 of step t+1).
        if (tid < 32) {
            float hn = 0.0f;
            if (tid < HPC) {
                const float rz = sh_rec[tid], rr = sh_rec[16 + tid], rh = sh_rec[32 + tid];
                const float xz = sh_x[par][tid], xr = sh_x[par][16 + tid], xh = sh_x[par][32 + tid];
                const float zt = sigmoidf_(xz + rz);
                const float rt = sigmoidf_(xr + rr);
                const float hh = sigmoidf_(xh + rt * rh);
                hn = zt * hprev + (1.0f - zt) * hh;
                hprev = hn;
                g_seq[(size_t)t * HH + blk * HPC + tid] = hn;
                int l = blk * HPC + tid;       // stage own slice for step t+1
                sh_h[(l >> 6) * 68 + (l & 63)] = hn;
            }
            // Pack 3 h-values + flag per chunk via shfl; one atomic 16B publish.
            float v0 = __shfl_sync(0xffffffffu, hn, (3 * tid) & 31);
            float v1 = __shfl_sync(0xffffffffu, hn, (3 * tid + 1) & 31);
            float v2 = __shfl_sync(0xffffffffu, hn, (3 * tid + 2) & 31);
            if (tid < NCH) {
                float4 o;
                o.x = v0; o.y = v1; o.z = v2;
                o.w = __uint_as_float((unsigned)(t + 1));
                st_rel128(&g_chunk[par ^ 1][blk][tid], o);
            }
        }
        // no bar3: step t+1's bar1 provides the intra-CTA ordering.
    }

    if (tid < HPC) out[HT_OFF + blk * HPC + tid] = hprev;
}

// ---------------- policy softmax + value head ----------------
__global__ __launch_bounds__(256)
void policy_value_kernel(const float* __restrict__ Wp, const float* __restrict__ bp,
                         const float* __restrict__ Wv, const float* __restrict__ bv,
                         float* __restrict__ out)
{
    __shared__ float srow[8][HH];
    const int warp = threadIdx.x >> 5;
    const int lane = threadIdx.x & 31;
    const int t = blockIdx.x * 8 + warp;

    const float4* rp = (const float4*)&g_seq[(size_t)t * HH];
    float4* sp = (float4*)&srow[warp][0];
    for (int i = lane; i < HH / 4; i += 32) sp[i] = rp[i];
    __syncwarp();

    const float* wcol; int stride; float acc;
    if (lane < AA)       { wcol = Wp + lane; stride = AA; acc = bp[lane]; }
    else if (lane == AA) { wcol = Wv;        stride = 1;  acc = bv[0];    }
    else                 { wcol = Wv;        stride = 0;  acc = 0.0f;     }

    #pragma unroll 4
    for (int k = 0; k < HH; k++)
        acc = fmaf(srow[warp][k], wcol[(size_t)k * stride], acc);

    float lv = (lane < AA) ? acc : -INFINITY;
    float m = lv;
    #pragma unroll
    for (int o = 16; o; o >>= 1) m = fmaxf(m, __shfl_xor_sync(0xffffffffu, m, o));
    float e = (lane < AA) ? __expf(acc - m) : 0.0f;
    float sum = e;
    #pragma unroll
    for (int o = 16; o; o >>= 1) sum += __shfl_xor_sync(0xffffffffu, sum, o);

    if (lane < AA)  out[P_OFF + (size_t)t * AA + lane] = e / sum;
    if (lane == AA) out[V_OFF + t] = acc;
}

// ---------------- launch ----------------
extern "C" void kernel_launch(void* const* d_in, const int* in_sizes, int n_in,
                              void* d_out, int out_size)
{
    (void)in_sizes; (void)n_in; (void)out_size;
    const float* x    = (const float*)d_in[0];
    const float* ph   = (const float*)d_in[1];
    const float* W1   = (const float*)d_in[2];
    const float* b1   = (const float*)d_in[3];
    const float* W2   = (const float*)d_in[4];
    const float* b2   = (const float*)d_in[5];
    const float* Wg   = (const float*)d_in[6];
    const float* Ug   = (const float*)d_in[7];
    const float* bg   = (const float*)d_in[8];
    const float* Wp   = (const float*)d_in[9];
    const float* bp   = (const float*)d_in[10];
    const float* Wv   = (const float*)d_in[11];
    const float* bv   = (const float*)d_in[12];
    float* out = (float*)d_out;

    float *z1, *z2, *X;
    cudaGetSymbolAddress((void**)&z1, g_z1);
    cudaGetSymbolAddress((void**)&z2, g_z2);
    cudaGetSymbolAddress((void**)&X,  g_X);

    sgemm_bias<true ><<<dim3(DD/128, TT/128), 256>>>(x,  W1, b1, z1, TT, DD, DIN);
    sgemm_bias<true ><<<dim3(DD/128, TT/128), 256>>>(z1, W2, b2, z2, TT, DD, DD);
    sgemm_bias<false><<<dim3(H3/128, TT/128), 256>>>(z2, Wg, bg, X,  TT, H3, DD);

    init_kernel<<<1, GC * NCH>>>(ph);
    gru_kernel<<<GC, GTHREADS>>>(Ug, bg, ph, out);
    policy_value_kernel<<<TT/8, 256>>>(Wp, bp, Wv, bv, out);
}

// round 14
// speedup vs baseline: 1.9073x; 1.0400x over previous
#include <cuda_runtime.h>
#include <math.h>

// Problem dims
#define TT   8192
#define DIN  2048
#define DD   512
#define HH   512
#define AA   18
#define H3   (3*HH)       // 1536

// GRU scan config: 32 persistent CTAs, 16 h-values each, 48 gate-cols each.
#define GC   32
#define HPC  16           // h per CTA
#define CPC  48           // rec columns per CTA (3 gates x 16)
#define NCH  6            // publish chunks per CTA (3 h-values + flag per 16B)
#define GTHREADS 384

// Output layout (flattened concat of (policy, value, hT))
#define P_OFF  0
#define V_OFF  (TT*AA)            // 147456
#define HT_OFF (TT*AA + TT)       // 155648

// ---------------- device scratch (no allocations allowed) ----------------
__device__ float g_z1[TT*DD];
__device__ float g_z2[TT*DD];
__device__ float g_X [TT*H3];
__device__ float g_seq[TT*HH];
// Publish buffer: one 128B line per (parity, producer). Each 16B chunk carries
// 3 h-values + the step flag in .w, written with ONE single-copy-atomic
// st.release.gpu.b128 — a matching flag implies valid payload in the same read.
__device__ __align__(128) float4 g_chunk[2][GC][8];

__device__ __forceinline__ float sigmoidf_(float x) {
    return 1.0f / (1.0f + __expf(-x));
}

// 16B single-copy-atomic RELAXED load (poll). Payload+flag arrive as one unit;
// no acquire needed: all communicated data is inside the atom, and the
// producer's release-store closes the cross-step causality chain.
__device__ __forceinline__ float4 ld_rlx128(const float4* p) {
    float4 v;
    asm volatile(
        "{\n\t"
        ".reg .b128 q;\n\t"
        ".reg .b64 lo, hi;\n\t"
        "ld.global.relaxed.gpu.b128 q, [%4];\n\t"
        "mov.b128 {lo, hi}, q;\n\t"
        "mov.b64 {%0, %1}, lo;\n\t"
        "mov.b64 {%2, %3}, hi;\n\t"
        "}"
        : "=f"(v.x), "=f"(v.y), "=f"(v.z), "=f"(v.w) : "l"(p));
    return v;
}
// 16B single-copy-atomic release store (publish). Orders this thread's prior
// flag-observation before the store -> no slot can be overwritten unseen.
__device__ __forceinline__ void st_rel128(float4* p, float4 v) {
    asm volatile(
        "{\n\t"
        ".reg .b128 q;\n\t"
        ".reg .b64 lo, hi;\n\t"
        "mov.b64 lo, {%1, %2};\n\t"
        "mov.b64 hi, {%3, %4};\n\t"
        "mov.b128 q, {lo, hi};\n\t"
        "st.global.release.gpu.b128 [%0], q;\n\t"
        "}"
        :: "l"(p), "f"(v.x), "f"(v.y), "f"(v.z), "f"(v.w) : "memory");
}

// Packed fp32x2 FMA (Blackwell FFMA2; PTX-only form). acc = w2*h2 + acc lanewise.
__device__ __forceinline__ void ffma2(unsigned long long& acc,
                                      unsigned long long w2,
                                      unsigned long long h2) {
    asm("fma.rn.f32x2 %0, %1, %2, %0;" : "+l"(acc) : "l"(w2), "l"(h2));
}
__device__ __forceinline__ unsigned long long pack2(float lo, float hi) {
    unsigned long long r;
    asm("mov.b64 %0, {%1, %2};" : "=l"(r) : "f"(lo), "f"(hi));
    return r;
}

// ---------------- fp32 SGEMM: C = act(A[MxK] @ B[KxN] + bias[N]) ----------------
template<bool RELU>
__global__ __launch_bounds__(256)
void sgemm_bias(const float* __restrict__ A, const float* __restrict__ B,
                const float* __restrict__ bias, float* __restrict__ C,
                int M, int N, int K)
{
    __shared__ float As[8][128];
    __shared__ float Bs[8][128];

    const int tid = threadIdx.x;
    const int bm = blockIdx.y * 128;
    const int bn = blockIdx.x * 128;

    const int arow = tid >> 1;
    const int acol = (tid & 1) << 2;
    const int brow = tid >> 5;
    const int bcol = (tid & 31) << 2;

    const int ty = tid >> 4, tx = tid & 15;
    const int row0 = ty << 3;
    const int col0 = tx << 3;

    float c[8][8];
    #pragma unroll
    for (int i = 0; i < 8; i++)
        #pragma unroll
        for (int j = 0; j < 8; j++) c[i][j] = 0.0f;

    for (int k0 = 0; k0 < K; k0 += 8) {
        float4 a4 = *(const float4*)&A[(size_t)(bm + arow) * K + k0 + acol];
        As[acol + 0][arow] = a4.x;
        As[acol + 1][arow] = a4.y;
        As[acol + 2][arow] = a4.z;
        As[acol + 3][arow] = a4.w;
        *(float4*)&Bs[brow][bcol] =
            *(const float4*)&B[(size_t)(k0 + brow) * N + bn + bcol];
        __syncthreads();

        #pragma unroll
        for (int kk = 0; kk < 8; kk++) {
            float4 a0 = *(const float4*)&As[kk][row0];
            float4 a1 = *(const float4*)&As[kk][row0 + 4];
            float4 b0 = *(const float4*)&Bs[kk][col0];
            float4 b1 = *(const float4*)&Bs[kk][col0 + 4];
            float ar[8] = {a0.x,a0.y,a0.z,a0.w,a1.x,a1.y,a1.z,a1.w};
            float br[8] = {b0.x,b0.y,b0.z,b0.w,b1.x,b1.y,b1.z,b1.w};
            #pragma unroll
            for (int i = 0; i < 8; i++)
                #pragma unroll
                for (int j = 0; j < 8; j++)
                    c[i][j] = fmaf(ar[i], br[j], c[i][j]);
        }
        __syncthreads();
    }

    #pragma unroll
    for (int i = 0; i < 8; i++) {
        #pragma unroll
        for (int j = 0; j < 8; j++) {
            float v = c[i][j] + bias[bn + col0 + j];
            if (RELU) v = fmaxf(v, 0.0f);
            C[(size_t)(bm + row0 + i) * N + bn + col0 + j] = v;
        }
    }
}

// ---------------- init: publish h0 (flag 0) into parity 0; clear parity 1 ----------------
__global__ void init_kernel(const float* __restrict__ prev_hidden)
{
    int t = threadIdx.x;                       // 192 threads = GC*NCH
    if (t < GC * NCH) {
        int p = t / NCH, c = t % NCH;
        int b = p * HPC + c * 3;
        float4 v;
        v.x = prev_hidden[b];
        v.y = (c * 3 + 1 < HPC) ? prev_hidden[b + 1] : 0.0f;
        v.z = (c * 3 + 2 < HPC) ? prev_hidden[b + 2] : 0.0f;
        v.w = __uint_as_float(0u);             // flag = step 0
        st_rel128(&g_chunk[0][p][c], v);
        // clear stale parity-1 flags from the previous graph replay;
        // flag 0 never matches an odd step number.
        float4 z = make_float4(0.0f, 0.0f, 0.0f, __uint_as_float(0u));
        st_rel128(&g_chunk[1][p][c], z);
    }
}

// ---------------- persistent GRU scan ----------------
// 32 CTAs x 384 threads. CTA `blk` owns h[blk*16 .. blk*16+16) -> 48 rec cols.
// tid = col*8 + seg: col 0..47, seg 0..7 (64-wide K segment, in lane bits 0..2
// so the K-reduction is 3 shfl_xor).
// Handoff: 16B atomic chunks {h0,h1,h2,flag}; relaxed-poll, release-publish.
// sh_h uses a 68-float seg stride so the 8 seg streams are bank-conflict-free.
// Dot uses packed fma.rn.f32x2 (FFMA2): 2x fp32 FMA throughput, identical numerics.
__global__ __launch_bounds__(GTHREADS, 1)
void gru_kernel(const float* __restrict__ Ug, const float* __restrict__ bg,
                const float* __restrict__ prev_hidden, float* __restrict__ out)
{
    __shared__ float sh_h[8 * 68];     // phys(l) = (l>>6)*68 + (l&63)
    __shared__ float sh_rec[CPC];
    __shared__ float sh_x[2][CPC];

    const int tid = threadIdx.x;
    const int blk = blockIdx.x;
    const int col = tid >> 3;          // 0..47
    const int seg = tid & 7;           // 0..7
    const int gate = col >> 4;         // 0..2
    const int j = col & 15;            // 0..15
    const int gcol = gate * HH + blk * HPC + j;

    // Weight slice packed as fp32 pairs: wp[i] = {Ug[seg*64+2i][gcol], Ug[seg*64+2i+1][gcol]}
    unsigned long long wp[32];
    #pragma unroll
    for (int i = 0; i < 32; i++) {
        float w0 = Ug[(size_t)(seg * 64 + 2 * i)     * H3 + gcol];
        float w1 = Ug[(size_t)(seg * 64 + 2 * i + 1) * H3 + gcol];
        wp[i] = pack2(w0, w1);
    }

    const float brec = bg[H3 + gcol];

    // Poller mapping: threads 0..185 each own one (producer != blk, chunk).
    const bool isPoll = (tid < (GC - 1) * NCH);
    int pp = 0, pc = 0, pbase = 0;
    if (isPoll) {
        int q = tid / NCH;
        pc = tid - q * NCH;
        pp = q + (q >= blk ? 1 : 0);
        pbase = pp * HPC + pc * 3;
    }
    // X loaders: threads 192..239 (disjoint from pollers). One step lookahead.
    const bool isX = (tid >= 192 && tid < 192 + CPC);
    const int xcol = tid - 192;
    const int xgc = (xcol >> 4) * HH + blk * HPC + (xcol & 15);
    float xv = 0.0f;
    if (isX) xv = g_X[xgc];                    // X[0]

    // Gate lanes (warp 0, lanes 0..15) keep their own h in a register.
    float hprev = 0.0f;
    if (tid < HPC) {
        hprev = prev_hidden[blk * HPC + tid];
        int l = blk * HPC + tid;               // stage own slice for t=0
        sh_h[(l >> 6) * 68 + (l & 63)] = hprev;
    }

    for (int t = 0; t < TT; t++) {
        const int par = t & 1;

        if (isX) {
            sh_x[par][xcol] = xv;              // stage prefetched X[t]
            if (t + 1 < TT)                    // issue X[t+1]; lands well before
                xv = g_X[(size_t)(t + 1) * H3 + xgc];   // next step's staging
        }

        if (isPoll) {
            const float4* cp = &g_chunk[par][pp][pc];
            float4 v;
            do { v = ld_rlx128(cp); } while (__float_as_uint(v.w) != (unsigned)t);
            int l0 = pbase;
            sh_h[(l0 >> 6) * 68 + (l0 & 63)] = v.x;
            if (pc * 3 + 1 < HPC) { int l = pbase + 1; sh_h[(l >> 6) * 68 + (l & 63)] = v.y; }
            if (pc * 3 + 2 < HPC) { int l = pbase + 2; sh_h[(l >> 6) * 68 + (l & 63)] = v.z; }
        }
        __syncthreads();                       // bar1: h + x staged

        // 512-long dot: 64 elems/thread as 32 packed FFMA2, 2 packed acc chains.
        // smem read as ulonglong2 -> aligned b64 register pairs, no repacking.
        const ulonglong2* hp = (const ulonglong2*)&sh_h[seg * 68];
        unsigned long long acc01 = 0ULL, acc23 = 0ULL;   // {0.f,0.f} bit pattern
        #pragma unroll
        for (int i = 0; i < 16; i++) {
            ulonglong2 hv = hp[i];
            ffma2(acc01, wp[2 * i],     hv.x);
            ffma2(acc23, wp[2 * i + 1], hv.y);
        }
        float a0, a1, a2, a3;
        asm("mov.b64 {%0, %1}, %2;" : "=f"(a0), "=f"(a1) : "l"(acc01));
        asm("mov.b64 {%0, %1}, %2;" : "=f"(a2), "=f"(a3) : "l"(acc23));
        float r = (a0 + a1) + (a2 + a3);
        r += __shfl_xor_sync(0xffffffffu, r, 1);
        r += __shfl_xor_sync(0xffffffffu, r, 2);
        r += __shfl_xor_sync(0xffffffffu, r, 4);
        if (seg == 0) sh_rec[col] = r + brec;
        __syncthreads();                       // bar2: rec ready

        // Warp 0: gates, PUBLISH FIRST, then local bookkeeping. Other warps run
        // ahead to the next poll (their sh writes target next-parity x /
        // foreign-producer h slots; reads fenced by bar1/bar2 of step t+1).
        if (tid < 32) {
            float hn = 0.0f;
            if (tid < HPC) {
                const float rz = sh_rec[tid], rr = sh_rec[16 + tid], rh = sh_rec[32 + tid];
                const float xz = sh_x[par][tid], xr = sh_x[par][16 + tid], xh = sh_x[par][32 + tid];
                const float zt = sigmoidf_(xz + rz);
                const float rt = sigmoidf_(xr + rr);
                const float hh = sigmoidf_(xh + rt * rh);
                hn = zt * hprev + (1.0f - zt) * hh;
            }
            // Pack 3 h-values + flag per chunk via shfl; one atomic 16B publish.
            float v0 = __shfl_sync(0xffffffffu, hn, (3 * tid) & 31);
            float v1 = __shfl_sync(0xffffffffu, hn, (3 * tid + 1) & 31);
            float v2 = __shfl_sync(0xffffffffu, hn, (3 * tid + 2) & 31);
            if (tid < NCH) {
                float4 o;
                o.x = v0; o.y = v1; o.z = v2;
                o.w = __uint_as_float((unsigned)(t + 1));
                st_rel128(&g_chunk[par ^ 1][blk][tid], o);
            }
            if (tid < HPC) {
                hprev = hn;
                g_seq[(size_t)t * HH + blk * HPC + tid] = hn;
                int l = blk * HPC + tid;       // stage own slice for step t+1
                sh_h[(l >> 6) * 68 + (l & 63)] = hn;
            }
        }
        // no bar3: step t+1's bar1 provides the intra-CTA ordering.
    }

    if (tid < HPC) out[HT_OFF + blk * HPC + tid] = hprev;
}

// ---------------- policy softmax + value head ----------------
__global__ __launch_bounds__(256)
void policy_value_kernel(const float* __restrict__ Wp, const float* __restrict__ bp,
                         const float* __restrict__ Wv, const float* __restrict__ bv,
                         float* __restrict__ out)
{
    __shared__ float srow[8][HH];
    const int warp = threadIdx.x >> 5;
    const int lane = threadIdx.x & 31;
    const int t = blockIdx.x * 8 + warp;

    const float4* rp = (const float4*)&g_seq[(size_t)t * HH];
    float4* sp = (float4*)&srow[warp][0];
    for (int i = lane; i < HH / 4; i += 32) sp[i] = rp[i];
    __syncwarp();

    const float* wcol; int stride; float acc;
    if (lane < AA)       { wcol = Wp + lane; stride = AA; acc = bp[lane]; }
    else if (lane == AA) { wcol = Wv;        stride = 1;  acc = bv[0];    }
    else                 { wcol = Wv;        stride = 0;  acc = 0.0f;     }

    #pragma unroll 4
    for (int k = 0; k < HH; k++)
        acc = fmaf(srow[warp][k], wcol[(size_t)k * stride], acc);

    float lv = (lane < AA) ? acc : -INFINITY;
    float m = lv;
    #pragma unroll
    for (int o = 16; o; o >>= 1) m = fmaxf(m, __shfl_xor_sync(0xffffffffu, m, o));
    float e = (lane < AA) ? __expf(acc - m) : 0.0f;
    float sum = e;
    #pragma unroll
    for (int o = 16; o; o >>= 1) sum += __shfl_xor_sync(0xffffffffu, sum, o);

    if (lane < AA)  out[P_OFF + (size_t)t * AA + lane] = e / sum;
    if (lane == AA) out[V_OFF + t] = acc;
}

// ---------------- launch ----------------
extern "C" void kernel_launch(void* const* d_in, const int* in_sizes, int n_in,
                              void* d_out, int out_size)
{
    (void)in_sizes; (void)n_in; (void)out_size;
    const float* x    = (const float*)d_in[0];
    const float* ph   = (const float*)d_in[1];
    const float* W1   = (const float*)d_in[2];
    const float* b1   = (const float*)d_in[3];
    const float* W2   = (const float*)d_in[4];
    const float* b2   = (const float*)d_in[5];
    const float* Wg   = (const float*)d_in[6];
    const float* Ug   = (const float*)d_in[7];
    const float* bg   = (const float*)d_in[8];
    const float* Wp   = (const float*)d_in[9];
    const float* bp   = (const float*)d_in[10];
    const float* Wv   = (const float*)d_in[11];
    const float* bv   = (const float*)d_in[12];
    float* out = (float*)d_out;

    float *z1, *z2, *X;
    cudaGetSymbolAddress((void**)&z1, g_z1);
    cudaGetSymbolAddress((void**)&z2, g_z2);
    cudaGetSymbolAddress((void**)&X,  g_X);

    sgemm_bias<true ><<<dim3(DD/128, TT/128), 256>>>(x,  W1, b1, z1, TT, DD, DIN);
    sgemm_bias<true ><<<dim3(DD/128, TT/128), 256>>>(z1, W2, b2, z2, TT, DD, DD);
    sgemm_bias<false><<<dim3(H3/128, TT/128), 256>>>(z2, Wg, bg, X,  TT, H3, DD);

    init_kernel<<<1, GC * NCH>>>(ph);
    gru_kernel<<<GC, GTHREADS>>>(Ug, bg, ph, out);
    policy_value_kernel<<<TT/8, 256>>>(Wp, bp, Wv, bv, out);
}

// round 15
// speedup vs baseline: 2.0336x; 1.0662x over previous
#include <cuda_runtime.h>
#include <math.h>

// Problem dims
#define TT   8192
#define DIN  2048
#define DD   512
#define HH   512
#define AA   18
#define H3   (3*HH)       // 1536

// GRU scan config: 64 persistent CTAs, 8 h-values each, 24 gate-cols each.
// (More CTAs => fewer cols/CTA => less smem h-delivery per step, which is the
//  measured-by-model bottleneck: delivered bytes = cols * 2KB @ 128B/cyc.)
#define GC   64
#define HPC  8            // h per CTA
#define CPC  24           // rec columns per CTA (3 gates x 8)
#define NCH  3            // publish chunks per CTA (3 h-values + flag per 16B)
#define GTHREADS 256

// Output layout (flattened concat of (policy, value, hT))
#define P_OFF  0
#define V_OFF  (TT*AA)            // 147456
#define HT_OFF (TT*AA + TT)       // 155648

// ---------------- device scratch (no allocations allowed) ----------------
__device__ float g_z1[TT*DD];
__device__ float g_z2[TT*DD];
__device__ float g_X [TT*H3];
__device__ float g_seq[TT*HH];
// Publish buffer: one 128B line per (parity, producer). Each 16B chunk carries
// 3 h-values + the step flag in .w, written with ONE single-copy-atomic
// st.release.gpu.b128 — a matching flag implies valid payload in the same read.
__device__ __align__(128) float4 g_chunk[2][GC][8];

__device__ __forceinline__ float sigmoidf_(float x) {
    return 1.0f / (1.0f + __expf(-x));
}

// 16B single-copy-atomic RELAXED load (poll). Payload+flag arrive as one unit.
__device__ __forceinline__ float4 ld_rlx128(const float4* p) {
    float4 v;
    asm volatile(
        "{\n\t"
        ".reg .b128 q;\n\t"
        ".reg .b64 lo, hi;\n\t"
        "ld.global.relaxed.gpu.b128 q, [%4];\n\t"
        "mov.b128 {lo, hi}, q;\n\t"
        "mov.b64 {%0, %1}, lo;\n\t"
        "mov.b64 {%2, %3}, hi;\n\t"
        "}"
        : "=f"(v.x), "=f"(v.y), "=f"(v.z), "=f"(v.w) : "l"(p));
    return v;
}
// 16B single-copy-atomic release store (publish).
__device__ __forceinline__ void st_rel128(float4* p, float4 v) {
    asm volatile(
        "{\n\t"
        ".reg .b128 q;\n\t"
        ".reg .b64 lo, hi;\n\t"
        "mov.b64 lo, {%1, %2};\n\t"
        "mov.b64 hi, {%3, %4};\n\t"
        "mov.b128 q, {lo, hi};\n\t"
        "st.global.release.gpu.b128 [%0], q;\n\t"
        "}"
        :: "l"(p), "f"(v.x), "f"(v.y), "f"(v.z), "f"(v.w) : "memory");
}

// Packed fp32x2 FMA (Blackwell FFMA2; PTX-only form). acc = w2*h2 + acc lanewise.
__device__ __forceinline__ void ffma2(unsigned long long& acc,
                                      unsigned long long w2,
                                      unsigned long long h2) {
    asm("fma.rn.f32x2 %0, %1, %2, %0;" : "+l"(acc) : "l"(w2), "l"(h2));
}
__device__ __forceinline__ unsigned long long pack2(float lo, float hi) {
    unsigned long long r;
    asm("mov.b64 %0, {%1, %2};" : "=l"(r) : "f"(lo), "f"(hi));
    return r;
}
__device__ __forceinline__ void unpack2(unsigned long long v, float& lo, float& hi) {
    asm("mov.b64 {%0, %1}, %2;" : "=f"(lo), "=f"(hi) : "l"(v));
}

// ---------------- fp32 SGEMM: C = act(A[MxK] @ B[KxN] + bias[N]) ----------------
// 128x128 tile, BK=8, 256 threads, 8x8 micro-tile. Inner product uses packed
// fma.rn.f32x2: 32 FFMA2 + 8 dup-packs per k-step instead of 64 FFMA (exact fp32).
template<bool RELU>
__global__ __launch_bounds__(256)
void sgemm_bias(const float* __restrict__ A, const float* __restrict__ B,
                const float* __restrict__ bias, float* __restrict__ C,
                int M, int N, int K)
{
    __shared__ float As[8][128];
    __shared__ float Bs[8][128];

    const int tid = threadIdx.x;
    const int bm = blockIdx.y * 128;
    const int bn = blockIdx.x * 128;

    const int arow = tid >> 1;
    const int acol = (tid & 1) << 2;
    const int brow = tid >> 5;
    const int bcol = (tid & 31) << 2;

    const int ty = tid >> 4, tx = tid & 15;
    const int row0 = ty << 3;
    const int col0 = tx << 3;

    unsigned long long c2[8][4];           // [row][col-pair], fp32x2 accumulators
    #pragma unroll
    for (int i = 0; i < 8; i++)
        #pragma unroll
        for (int j = 0; j < 4; j++) c2[i][j] = 0ULL;

    for (int k0 = 0; k0 < K; k0 += 8) {
        float4 a4 = *(const float4*)&A[(size_t)(bm + arow) * K + k0 + acol];
        As[acol + 0][arow] = a4.x;
        As[acol + 1][arow] = a4.y;
        As[acol + 2][arow] = a4.z;
        As[acol + 3][arow] = a4.w;
        *(float4*)&Bs[brow][bcol] =
            *(const float4*)&B[(size_t)(k0 + brow) * N + bn + bcol];
        __syncthreads();

        #pragma unroll
        for (int kk = 0; kk < 8; kk++) {
            float4 a0 = *(const float4*)&As[kk][row0];
            float4 a1 = *(const float4*)&As[kk][row0 + 4];
            const ulonglong2* bp = (const ulonglong2*)&Bs[kk][col0];
            ulonglong2 b01 = bp[0];
            ulonglong2 b23 = bp[1];
            float ar[8] = {a0.x,a0.y,a0.z,a0.w,a1.x,a1.y,a1.z,a1.w};
            #pragma unroll
            for (int i = 0; i < 8; i++) {
                unsigned long long ad = pack2(ar[i], ar[i]);
                ffma2(c2[i][0], ad, b01.x);
                ffma2(c2[i][1], ad, b01.y);
                ffma2(c2[i][2], ad, b23.x);
                ffma2(c2[i][3], ad, b23.y);
            }
        }
        __syncthreads();
    }

    #pragma unroll
    for (int i = 0; i < 8; i++) {
        #pragma unroll
        for (int j = 0; j < 4; j++) {
            float lo, hi;
            unpack2(c2[i][j], lo, hi);
            float v0 = lo + bias[bn + col0 + 2 * j];
            float v1 = hi + bias[bn + col0 + 2 * j + 1];
            if (RELU) { v0 = fmaxf(v0, 0.0f); v1 = fmaxf(v1, 0.0f); }
            float2 o = make_float2(v0, v1);
            *(float2*)&C[(size_t)(bm + row0 + i) * N + bn + col0 + 2 * j] = o;
        }
    }
}

// ---------------- init: publish h0 (flag 0) into parity 0; clear parity 1 ----------------
__global__ void init_kernel(const float* __restrict__ prev_hidden)
{
    int t = threadIdx.x;                       // GC*NCH = 192 threads
    if (t < GC * NCH) {
        int p = t / NCH, c = t % NCH;
        int b = p * HPC + c * 3;
        float4 v;
        v.x = prev_hidden[b];
        v.y = (c * 3 + 1 < HPC) ? prev_hidden[b + 1] : 0.0f;
        v.z = (c * 3 + 2 < HPC) ? prev_hidden[b + 2] : 0.0f;
        v.w = __uint_as_float(0u);             // flag = step 0
        st_rel128(&g_chunk[0][p][c], v);
        // clear stale parity-1 flags from the previous graph replay;
        // flag 0 never matches an odd step number.
        float4 z = make_float4(0.0f, 0.0f, 0.0f, __uint_as_float(0u));
        st_rel128(&g_chunk[1][p][c], z);
    }
}

// ---------------- persistent GRU scan ----------------
// 64 CTAs x 256 threads. CTA `blk` owns h[blk*8 .. blk*8+8) -> 24 rec cols.
// Compute threads 0..191: tid = col*8 + seg (col 0..23, seg 0..7 in lane bits
// so the K-reduction is 3 shfl_xor). Pollers overlay threads 0..188; X loaders
// are threads 224..247 (disjoint from pollers, one-step register lookahead).
// Handoff: 16B atomic chunks {h0,h1,h2,flag}; relaxed-poll, release-publish.
// sh_h: 68-float seg stride keeps the 8 seg streams bank-conflict-free.
__global__ __launch_bounds__(GTHREADS, 1)
void gru_kernel(const float* __restrict__ Ug, const float* __restrict__ bg,
                const float* __restrict__ prev_hidden, float* __restrict__ out)
{
    __shared__ float sh_h[8 * 68];     // phys(l) = (l>>6)*68 + (l&63)
    __shared__ float sh_rec[CPC];
    __shared__ float sh_x[2][CPC];

    const int tid = threadIdx.x;
    const int blk = blockIdx.x;
    const bool isC = (tid < CPC * 8);  // 192 compute threads
    const int col = tid >> 3;          // 0..23 (compute)
    const int seg = tid & 7;           // 0..7
    const int gate = col >> 3;         // 0..2
    const int j = col & 7;             // 0..7
    const int gcol = gate * HH + blk * HPC + j;

    // Weight slice packed as fp32 pairs: wp[i] = {Ug[seg*64+2i][gcol], Ug[seg*64+2i+1][gcol]}
    unsigned long long wp[32];
    if (isC) {
        #pragma unroll
        for (int i = 0; i < 32; i++) {
            float w0 = Ug[(size_t)(seg * 64 + 2 * i)     * H3 + gcol];
            float w1 = Ug[(size_t)(seg * 64 + 2 * i + 1) * H3 + gcol];
            wp[i] = pack2(w0, w1);
        }
    }
    const float brec = isC ? bg[H3 + gcol] : 0.0f;

    // Poller mapping: threads 0..(63*3-1)=188 each own one (producer != blk, chunk).
    const bool isPoll = (tid < (GC - 1) * NCH);
    int pp = 0, pc = 0, pbase = 0;
    if (isPoll) {
        int q = tid / NCH;
        pc = tid - q * NCH;
        pp = q + (q >= blk ? 1 : 0);
        pbase = pp * HPC + pc * 3;
    }
    // X loaders: threads 224..247 (disjoint from pollers). One step lookahead.
    const bool isX = (tid >= 224 && tid < 224 + CPC);
    const int xcol = tid - 224;
    const int xgc = (xcol >> 3) * HH + blk * HPC + (xcol & 7);
    float xv = 0.0f;
    if (isX) xv = g_X[xgc];                    // X[0]

    // Gate lanes (warp 0, lanes 0..7) keep their own h in a register.
    float hprev = 0.0f;
    if (tid < HPC) {
        hprev = prev_hidden[blk * HPC + tid];
        int l = blk * HPC + tid;               // stage own slice for t=0
        sh_h[(l >> 6) * 68 + (l & 63)] = hprev;
    }

    for (int t = 0; t < TT; t++) {
        const int par = t & 1;

        if (isX) {
            sh_x[par][xcol] = xv;              // stage prefetched X[t]
            if (t + 1 < TT)
                xv = g_X[(size_t)(t + 1) * H3 + xgc];
        }

        if (isPoll) {
            const float4* cp = &g_chunk[par][pp][pc];
            float4 v;
            do { v = ld_rlx128(cp); } while (__float_as_uint(v.w) != (unsigned)t);
            int l0 = pbase;
            sh_h[(l0 >> 6) * 68 + (l0 & 63)] = v.x;
            if (pc * 3 + 1 < HPC) { int l = pbase + 1; sh_h[(l >> 6) * 68 + (l & 63)] = v.y; }
            if (pc * 3 + 2 < HPC) { int l = pbase + 2; sh_h[(l >> 6) * 68 + (l & 63)] = v.z; }
        }
        __syncthreads();                       // bar1: h + x staged

        // 512-long dot (compute threads): 64 elems as 32 packed FFMA2.
        if (isC) {
            const ulonglong2* hp = (const ulonglong2*)&sh_h[seg * 68];
            unsigned long long acc01 = 0ULL, acc23 = 0ULL;
            #pragma unroll
            for (int i = 0; i < 16; i++) {
                ulonglong2 hv = hp[i];
                ffma2(acc01, wp[2 * i],     hv.x);
                ffma2(acc23, wp[2 * i + 1], hv.y);
            }
            float a0, a1, a2, a3;
            unpack2(acc01, a0, a1);
            unpack2(acc23, a2, a3);
            float r = (a0 + a1) + (a2 + a3);
            r += __shfl_xor_sync(0xffffffffu, r, 1);
            r += __shfl_xor_sync(0xffffffffu, r, 2);
            r += __shfl_xor_sync(0xffffffffu, r, 4);
            if (seg == 0) sh_rec[col] = r + brec;
        }
        __syncthreads();                       // bar2: rec ready

        // Warp 0: gates, publish first, then local bookkeeping. Other warps run
        // ahead to the next poll (their sh writes target next-parity x /
        // foreign-producer h slots; reads fenced by bar1/bar2 of step t+1).
        if (tid < 32) {
            float hn = 0.0f;
            if (tid < HPC) {
                const float rz = sh_rec[tid], rr = sh_rec[8 + tid], rh = sh_rec[16 + tid];
                const float xz = sh_x[par][tid], xr = sh_x[par][8 + tid], xh = sh_x[par][16 + tid];
                const float zt = sigmoidf_(xz + rz);
                const float rt = sigmoidf_(xr + rr);
                const float hh = sigmoidf_(xh + rt * rh);
                hn = zt * hprev + (1.0f - zt) * hh;
            }
            // Pack 3 h-values + flag per chunk via shfl; one atomic 16B publish.
            float v0 = __shfl_sync(0xffffffffu, hn, (3 * tid) & 31);
            float v1 = __shfl_sync(0xffffffffu, hn, (3 * tid + 1) & 31);
            float v2 = __shfl_sync(0xffffffffu, hn, (3 * tid + 2) & 31);
            if (tid < NCH) {
                float4 o;
                o.x = v0; o.y = v1; o.z = v2;
                o.w = __uint_as_float((unsigned)(t + 1));
                st_rel128(&g_chunk[par ^ 1][blk][tid], o);
            }
            if (tid < HPC) {
                hprev = hn;
                g_seq[(size_t)t * HH + blk * HPC + tid] = hn;
                int l = blk * HPC + tid;       // stage own slice for step t+1
                sh_h[(l >> 6) * 68 + (l & 63)] = hn;
            }
        }
        // no bar3: step t+1's bar1 provides the intra-CTA ordering.
    }

    if (tid < HPC) out[HT_OFF + blk * HPC + tid] = hprev;
}

// ---------------- policy softmax + value head ----------------
__global__ __launch_bounds__(256)
void policy_value_kernel(const float* __restrict__ Wp, const float* __restrict__ bp,
                         const float* __restrict__ Wv, const float* __restrict__ bv,
                         float* __restrict__ out)
{
    __shared__ float srow[8][HH];
    const int warp = threadIdx.x >> 5;
    const int lane = threadIdx.x & 31;
    const int t = blockIdx.x * 8 + warp;

    const float4* rp = (const float4*)&g_seq[(size_t)t * HH];
    float4* sp = (float4*)&srow[warp][0];
    for (int i = lane; i < HH / 4; i += 32) sp[i] = rp[i];
    __syncwarp();

    const float* wcol; int stride; float acc;
    if (lane < AA)       { wcol = Wp + lane; stride = AA; acc = bp[lane]; }
    else if (lane == AA) { wcol = Wv;        stride = 1;  acc = bv[0];    }
    else                 { wcol = Wv;        stride = 0;  acc = 0.0f;     }

    #pragma unroll 4
    for (int k = 0; k < HH; k++)
        acc = fmaf(srow[warp][k], wcol[(size_t)k * stride], acc);

    float lv = (lane < AA) ? acc : -INFINITY;
    float m = lv;
    #pragma unroll
    for (int o = 16; o; o >>= 1) m = fmaxf(m, __shfl_xor_sync(0xffffffffu, m, o));
    float e = (lane < AA) ? __expf(acc - m) : 0.0f;
    float sum = e;
    #pragma unroll
    for (int o = 16; o; o >>= 1) sum += __shfl_xor_sync(0xffffffffu, sum, o);

    if (lane < AA)  out[P_OFF + (size_t)t * AA + lane] = e / sum;
    if (lane == AA) out[V_OFF + t] = acc;
}

// ---------------- launch ----------------
extern "C" void kernel_launch(void* const* d_in, const int* in_sizes, int n_in,
                              void* d_out, int out_size)
{
    (void)in_sizes; (void)n_in; (void)out_size;
    const float* x    = (const float*)d_in[0];
    const float* ph   = (const float*)d_in[1];
    const float* W1   = (const float*)d_in[2];
    const float* b1   = (const float*)d_in[3];
    const float* W2   = (const float*)d_in[4];
    const float* b2   = (const float*)d_in[5];
    const float* Wg   = (const float*)d_in[6];
    const float* Ug   = (const float*)d_in[7];
    const float* bg   = (const float*)d_in[8];
    const float* Wp   = (const float*)d_in[9];
    const float* bp   = (const float*)d_in[10];
    const float* Wv   = (const float*)d_in[11];
    const float* bv   = (const float*)d_in[12];
    float* out = (float*)d_out;

    float *z1, *z2, *X;
    cudaGetSymbolAddress((void**)&z1, g_z1);
    cudaGetSymbolAddress((void**)&z2, g_z2);
    cudaGetSymbolAddress((void**)&X,  g_X);

    sgemm_bias<true ><<<dim3(DD/128, TT/128), 256>>>(x,  W1, b1, z1, TT, DD, DIN);
    sgemm_bias<true ><<<dim3(DD/128, TT/128), 256>>>(z1, W2, b2, z2, TT, DD, DD);
    sgemm_bias<false><<<dim3(H3/128, TT/128), 256>>>(z2, Wg, bg, X,  TT, H3, DD);

    init_kernel<<<1, GC * NCH>>>(ph);
    gru_kernel<<<GC, GTHREADS>>>(Ug, bg, ph, out);
    policy_value_kernel<<<TT/8, 256>>>(Wp, bp, Wv, bv, out);
}